// round 16
// baseline (speedup 1.0000x reference)
#include <cuda_runtime.h>
#include <cuda_bf16.h>
#include <cstdint>

typedef unsigned long long ull;

// ===================== constants =====================
#define TDL  128
#define AST  144
#define R_AHI 0
#define R_ALO 18432
#define R_BHI 36864
#define R_BLO 46080
#define STAGE 55296
#define SMEM_MMA (2 * STAGE)     // 110592 -> 2 blocks/SM
#define HMAX 64
#define LMAX 16384
#define PRMAX 4096
#define LSPLIT 2048
#define KS_HEAVY 6
#define KS_LIGHT 2

__device__ float    g_sf[5][HMAX * LMAX];          // partial buffers
__device__ uint32_t g_whi32[HMAX * PRMAX];
__device__ uint32_t g_wlo32[HMAX * PRMAX];

__device__ __forceinline__ uint32_t smem_u32(const void* p) {
    uint32_t a;
    asm("{ .reg .u64 t; cvta.to.shared.u64 t, %1; cvt.u32.u64 %0, t; }"
        : "=r"(a) : "l"(p));
    return a;
}
__device__ __forceinline__ uint32_t prmt_(uint32_t a, uint32_t b, uint32_t sel) {
    uint32_t d;
    asm("prmt.b32 %0, %1, %2, %3;" : "=r"(d) : "r"(a), "r"(b), "r"(sel));
    return d;
}
__device__ __forceinline__ uint32_t cvt_bf16x2(float hi_elem, float lo_elem) {
    uint32_t d;
    asm("cvt.rn.bf16x2.f32 %0, %1, %2;" : "=r"(d) : "f"(hi_elem), "f"(lo_elem));
    return d;
}
__device__ __forceinline__ void ldm_x4(uint32_t* r, uint32_t addr) {
    asm volatile("ldmatrix.sync.aligned.m8n8.x4.shared.b16 {%0,%1,%2,%3}, [%4];"
                 : "=r"(r[0]), "=r"(r[1]), "=r"(r[2]), "=r"(r[3]) : "r"(addr));
}
__device__ __forceinline__ void mma_bf16(float* c, const uint32_t* a,
                                         uint32_t b0, uint32_t b1) {
    asm volatile(
        "mma.sync.aligned.m16n8k16.row.col.f32.bf16.bf16.f32 "
        "{%0,%1,%2,%3}, {%4,%5,%6,%7}, {%8,%9}, {%0,%1,%2,%3};"
        : "+f"(c[0]), "+f"(c[1]), "+f"(c[2]), "+f"(c[3])
        : "r"(a[0]), "r"(a[1]), "r"(a[2]), "r"(a[3]), "r"(b0), "r"(b1));
}

// ===================== W pre-split =====================
__global__ void w_split_kernel(const float* __restrict__ W, int P, int H, int Pr)
{
    int total = HMAX * Pr;
    for (int idx = blockIdx.x * blockDim.x + threadIdx.x; idx < total;
         idx += gridDim.x * blockDim.x) {
        int h = idx / Pr, p = idx % Pr;
        float wr = 0.f, wi = 0.f;
        if (h < H && p < P) {
            float2 w = *(const float2*)(W + ((size_t)h * P + p) * 2);
            wr = w.x; wi = -w.y;
        }
        uint32_t ur = __float_as_uint(wr), ui = __float_as_uint(wi);
        float hr = __uint_as_float(ur & 0xffff0000u);
        float hs = __uint_as_float(ui & 0xffff0000u);
        g_whi32[h * Pr + p] = prmt_(ur, ui, 0x7632);
        g_wlo32[h * Pr + p] = cvt_bf16x2(wi - hs, wr - hr);
    }
}

// ===================== A' chunk synthesis (prologue) =====================
__device__ __forceinline__ void synth_chunk(char* stage, const float* __restrict__ A,
                                            int p0, int P, int l0, int lane, int seg,
                                            bool p3)
{
    char* aHi = stage + R_AHI;
    char* aLo = stage + R_ALO;
    int p = p0 + lane;
    float vr = 0.f, vi = 0.f, axr = 0.f, axi = 0.f;
    if (p < P) {
        float2 a = *(const float2*)(A + 2 * p);
        axr = a.x; axi = a.y;
        float lr = 0.5f * logf(a.x * a.x + a.y * a.y);
        float th = atan2f(a.y, a.x);
        float e = (float)(l0 + seg * 16);
        float mag = expf(lr * e);
        float sp, cp;
        sincosf(th * e, &sp, &cp);
        vr = mag * cp; vi = mag * sp;
    }
#pragma unroll
    for (int j = 0; j < 16; ++j) {
        int l = seg * 16 + j;
        uint32_t ur = __float_as_uint(vr), ui = __float_as_uint(vi);
        *(uint32_t*)(aHi + l * AST + 4 * lane) = prmt_(ur, ui, 0x7632);
        if (p3) {
            float hr = __uint_as_float(ur & 0xffff0000u);
            float hs = __uint_as_float(ui & 0xffff0000u);
            *(uint32_t*)(aLo + l * AST + 4 * lane) = cvt_bf16x2(vi - hs, vr - hr);
        }
        float nvr = vr * axr - vi * axi;
        float nvi = vr * axi + vi * axr;
        vr = nvr; vi = nvi;
    }
}

// ===================== main HMMA kernel: balanced jobs =====================
extern __shared__ char smem_raw[];

__global__ void __launch_bounds__(256, 2)
mv_mma6_kernel(const float* __restrict__ A, float* __restrict__ out,
               int P, int H, int L, int Pr, long long out_cap, int nheavy)
{
    char* smem = smem_raw;
    const uint32_t sb = smem_u32(smem);
    const int tid  = threadIdx.x;
    const int lane = tid & 31;
    const int wid  = tid >> 5;
    const int wm   = wid & 3;
    const int wn   = wid >> 2;

    // ---- decode job (heavy jobs first) ----
    const int jid = blockIdx.x;
    const int nhj = nheavy * KS_HEAVY;
    const int nch_tot = Pr / 32;
    int tile, k, nsplit;
    bool p3;
    if (jid < nhj) {
        tile = jid / KS_HEAVY; k = jid % KS_HEAVY;
        nsplit = KS_HEAVY; p3 = true;
    } else {
        int e = jid - nhj;
        tile = nheavy + e / KS_LIGHT; k = e % KS_LIGHT;
        nsplit = KS_LIGHT; p3 = false;
    }
    const int l0 = tile * TDL;

    float* dst; long long cap;
    if (k == 0) { dst = out; cap = out_cap; }
    else        { dst = g_sf[k - 1]; cap = (long long)HMAX * LMAX; }

    const int cpb = (nch_tot + nsplit - 1) / nsplit;
    const int cB = k * cpb;
    const int cE = min(nch_tot, cB + cpb);

    const uint32_t aRel = (uint32_t)((wm * 32 + (lane & 15)) * AST + ((lane >> 4) << 4));
    const int bRow = wn * 32 + ((lane >> 4) << 3) + (lane & 7);
    const uint32_t bRel = (uint32_t)(bRow * AST + ((lane & 8) ? 16 : 0));

    float acc[2][4][4];
#pragma unroll
    for (int mi = 0; mi < 2; ++mi)
#pragma unroll
        for (int j = 0; j < 4; ++j)
#pragma unroll
            for (int q = 0; q < 4; ++q) acc[mi][j][q] = 0.f;

    const int nT = p3 ? 4 : 2;

    // ---- prologue: fill stage 0 ----
    if (cB < cE) {
        for (int t = 0; t < nT; ++t) {
            int idx = tid + 256 * t;
            int hi_buf = (idx < 512);
            int id2 = idx & 511;
            int h = id2 >> 3, q = id2 & 7;
            const uint32_t* src = (hi_buf ? g_whi32 : g_wlo32) + h * Pr + cB * 32;
            uint4 v = ((const uint4*)src)[q];
            *(uint4*)(smem + (hi_buf ? R_BHI : R_BLO) + h * AST + q * 16) = v;
        }
        synth_chunk(smem, A, cB * 32, P, l0, lane, wid, p3);
    }
    __syncthreads();

    // ---- main loop: MMA(cur) interleaved with synth(next) ----
    for (int c = cB; c < cE; ++c) {
        const int st = (c - cB) & 1;
        char* nxt = smem + (st ^ 1) * STAGE;
        const bool havenext = (c + 1 < cE);

        uint4 wv[4];
        if (havenext) {
            for (int t = 0; t < nT; ++t) {
                int idx = tid + 256 * t;
                int id2 = idx & 511;
                int h = id2 >> 3, q = id2 & 7;
                const uint32_t* src = ((idx < 512) ? g_whi32 : g_wlo32)
                                      + h * Pr + (c + 1) * 32;
                wv[t] = ((const uint4*)src)[q];
            }
        }

        const uint32_t sbase = sb + st * STAGE;
        const uint32_t aHiB = sbase + R_AHI + aRel;
        const uint32_t aLoB = sbase + R_ALO + aRel;
        const uint32_t bHiB = sbase + R_BHI + bRel;
        const uint32_t bLoB = sbase + R_BLO + bRel;

        float vr = 0.f, vi = 0.f, axr = 0.f, axi = 0.f;
        char* aHiN = nxt + R_AHI;
        char* aLoN = nxt + R_ALO;
        const int p_n = (c + 1) * 32 + lane;

#pragma unroll
        for (int ks = 0; ks < 4; ++ks) {
            const uint32_t kb = ks * 32;
            uint32_t ah0[4], ah1[4];
            ldm_x4(ah0, aHiB + kb);
            ldm_x4(ah1, aHiB + 16 * AST + kb);
            uint32_t bh[8];
            ldm_x4(bh,     bHiB + kb);
            ldm_x4(bh + 4, bHiB + 16 * AST + kb);

            if (p3) {
                uint32_t al0[4], al1[4], bl[8];
                ldm_x4(al0, aLoB + kb);
                ldm_x4(al1, aLoB + 16 * AST + kb);
                ldm_x4(bl,     bLoB + kb);
                ldm_x4(bl + 4, bLoB + 16 * AST + kb);
#pragma unroll
                for (int j = 0; j < 4; ++j) {
                    mma_bf16(acc[0][j], ah0, bh[2 * j], bh[2 * j + 1]);
                    mma_bf16(acc[0][j], ah0, bl[2 * j], bl[2 * j + 1]);
                    mma_bf16(acc[0][j], al0, bh[2 * j], bh[2 * j + 1]);
                    mma_bf16(acc[1][j], ah1, bh[2 * j], bh[2 * j + 1]);
                    mma_bf16(acc[1][j], ah1, bl[2 * j], bl[2 * j + 1]);
                    mma_bf16(acc[1][j], al1, bh[2 * j], bh[2 * j + 1]);
                }
            } else {
#pragma unroll
                for (int j = 0; j < 4; ++j) {
                    mma_bf16(acc[0][j], ah0, bh[2 * j], bh[2 * j + 1]);
                    mma_bf16(acc[1][j], ah1, bh[2 * j], bh[2 * j + 1]);
                }
            }

            if (havenext) {
                if (ks == 0) {
                    if (p_n < P) {
                        float2 a = *(const float2*)(A + 2 * p_n);
                        axr = a.x; axi = a.y;
                        float lr = 0.5f * logf(a.x * a.x + a.y * a.y);
                        float th = atan2f(a.y, a.x);
                        float e = (float)(l0 + wid * 16);
                        float mag = expf(lr * e);
                        float sp, cp;
                        sincosf(th * e, &sp, &cp);
                        vr = mag * cp; vi = mag * sp;
                    } else { vr = vi = axr = axi = 0.f; }
                }
#pragma unroll
                for (int j = 0; j < 4; ++j) {
                    int l = wid * 16 + ks * 4 + j;
                    uint32_t ur = __float_as_uint(vr), ui = __float_as_uint(vi);
                    *(uint32_t*)(aHiN + l * AST + 4 * lane) = prmt_(ur, ui, 0x7632);
                    if (p3) {
                        float hr = __uint_as_float(ur & 0xffff0000u);
                        float hs = __uint_as_float(ui & 0xffff0000u);
                        *(uint32_t*)(aLoN + l * AST + 4 * lane) = cvt_bf16x2(vi - hs, vr - hr);
                    }
                    float nvr = vr * axr - vi * axi;
                    float nvi = vr * axi + vi * axr;
                    vr = nvr; vi = nvi;
                }
                if (ks < nT) {
                    int idx = tid + 256 * ks;
                    int hi_buf = (idx < 512);
                    int id2 = idx & 511;
                    int h = id2 >> 3, q = id2 & 7;
                    *(uint4*)(nxt + (hi_buf ? R_BHI : R_BLO) + h * AST + q * 16) = wv[ks];
                }
            }
        }
        __syncthreads();
    }

    // ---- epilogue ----
    const int trow  = lane >> 2;
    const int tcol2 = (lane & 3) * 2;
#pragma unroll
    for (int mi = 0; mi < 2; ++mi) {
        int lA = l0 + wm * 32 + mi * 16 + trow;
        int lB = lA + 8;
#pragma unroll
        for (int j = 0; j < 4; ++j) {
            int h0 = wn * 32 + j * 8 + tcol2;
            int h1 = h0 + 1;
            if (h0 < H) {
                if (lA < L) { long long f = (long long)h0 * L + lA; if (f < cap) dst[f] = acc[mi][j][0]; }
                if (lB < L) { long long f = (long long)h0 * L + lB; if (f < cap) dst[f] = acc[mi][j][2]; }
            }
            if (h1 < H) {
                if (lA < L) { long long f = (long long)h1 * L + lA; if (f < cap) dst[f] = acc[mi][j][1]; }
                if (lB < L) { long long f = (long long)h1 * L + lB; if (f < cap) dst[f] = acc[mi][j][3]; }
            }
        }
    }
}

// out += s0 (all cols); heavy cols also += s1..s4
__global__ void combine4_kernel(float* __restrict__ out, long long n4, int L4)
{
    const float4* s0 = (const float4*)g_sf[0];
    const float4* s1 = (const float4*)g_sf[1];
    const float4* s2 = (const float4*)g_sf[2];
    const float4* s3 = (const float4*)g_sf[3];
    const float4* s4 = (const float4*)g_sf[4];
    float4* o4 = (float4*)out;
    const int Ls4 = LSPLIT / 4;
    long long i = (long long)blockIdx.x * blockDim.x + threadIdx.x;
    long long stride = (long long)gridDim.x * blockDim.x;
    for (; i < n4; i += stride) {
        int lq = (int)(i % L4);
        float4 a = o4[i], b = s0[i];
        a.x += b.x; a.y += b.y; a.z += b.z; a.w += b.w;
        if (lq < Ls4) {
            float4 c = s1[i], d = s2[i], e = s3[i], f = s4[i];
            a.x += c.x + d.x + e.x + f.x;
            a.y += c.y + d.y + e.y + f.y;
            a.z += c.z + d.z + e.z + f.z;
            a.w += c.w + d.w + e.w + f.w;
        }
        o4[i] = a;
    }
}

// ================= SIMT fallback (R9, known-good, non-conforming shapes) =================
#define KC 32
#define TL 128
#define VSTRIDE 130
#define FB_NT 256

__device__ __forceinline__ ull pk2(float lo, float hi) {
    ull r; asm("mov.b64 %0, {%1, %2};" : "=l"(r) : "f"(lo), "f"(hi)); return r;
}
__device__ __forceinline__ void upk2(ull v, float& lo, float& hi) {
    asm("mov.b64 {%0, %1}, %2;" : "=f"(lo), "=f"(hi) : "l"(v));
}
__device__ __forceinline__ void fma2(ull& d, ull a, ull b) {
    asm("fma.rn.f32x2 %0, %1, %2, %3;" : "=l"(d) : "l"(a), "l"(b), "l"(d));
}
#define V_BYTES   (KC * VSTRIDE * 8)
#define WP_BYTES  ((HMAX / 2) * KC * 16)
#define FB_SMEM_FIXED (V_BYTES + WP_BYTES)

__global__ void __launch_bounds__(FB_NT, 2)
mv_gemm_kernel(const float* __restrict__ A, const float* __restrict__ W,
               float* __restrict__ out, int P, int H, int L,
               long long out_cap)
{
    extern __shared__ char smem[];
    float2* Vc = (float2*)smem;
    float4* Wp = (float4*)(smem + V_BYTES);
    float2* Ls = (float2*)(smem + FB_SMEM_FIXED);

    const int tid  = threadIdx.x;
    const int l0   = blockIdx.x * TL;
    const int lane = tid & 31;
    const int wid  = tid >> 5;
    const int wg   = wid & 3;
    const int cg   = wid >> 2;
    const int c0   = cg * 64 + lane;
    const int c1   = c0 + 32;

    for (int p = tid; p < P; p += FB_NT) {
        float ar = A[2 * p], ai = A[2 * p + 1];
        Ls[p] = make_float2(0.5f * logf(ar * ar + ai * ai), atan2f(ai, ar));
    }
    __syncthreads();

    ull acc[8][2];
#pragma unroll
    for (int s = 0; s < 8; ++s) { acc[s][0] = 0ull; acc[s][1] = 0ull; }

    const int nchunks = (P + KC - 1) / KC;
#pragma unroll 1
    for (int c = 0; c < nchunks; ++c) {
        const int p0 = c * KC;
#pragma unroll
        for (int i = 0; i < (KC * HMAX / 2) / FB_NT; ++i) {
            int idx = tid + FB_NT * i;
            int hp = idx >> 5, pl = idx & 31, p = p0 + pl;
            int h0 = 2 * hp, h1 = 2 * hp + 1;
            float wr0 = 0.f, wi0 = 0.f, wr1 = 0.f, wi1 = 0.f;
            if (p < P) {
                if (h0 < H) { float2 w = *(const float2*)(W + ((size_t)h0 * P + p) * 2); wr0 = w.x; wi0 = w.y; }
                if (h1 < H) { float2 w = *(const float2*)(W + ((size_t)h1 * P + p) * 2); wr1 = w.x; wi1 = w.y; }
            }
            Wp[hp * KC + pl] = make_float4(wr0, wr1, -wi0, -wi1);
        }
#pragma unroll
        for (int i = 0; i < 2; ++i) {
            int slot = tid + FB_NT * i;
            int fseg = slot >> 5, flane = slot & 31;
            const int p = p0 + flane;
            float vr = 0.f, vi = 0.f, axr = 0.f, axi = 0.f;
            if (p < P) {
                float2 lt = Ls[p];
                axr = A[2 * p]; axi = A[2 * p + 1];
                const float e = (float)(l0 + fseg * 8);
                float mag = expf(lt.x * e);
                float sp, cp; sincosf(lt.y * e, &sp, &cp);
                vr = mag * cp; vi = mag * sp;
            }
#pragma unroll
            for (int jp = 0; jp < 4; ++jp) {
                float vr1 = vr * axr - vi * axi;
                float vi1 = vr * axi + vi * axr;
                *(float4*)&Vc[flane * VSTRIDE + fseg * 8 + 2 * jp] = make_float4(vr, vi, vr1, vi1);
                vr = vr1 * axr - vi1 * axi;
                vi = vr1 * axi + vi1 * axr;
            }
        }
        __syncthreads();
#pragma unroll 4
        for (int kk = 0; kk < KC; ++kk) {
            float2 a0 = Vc[kk * VSTRIDE + c0];
            float2 a1 = Vc[kk * VSTRIDE + c1];
            ull vrr0 = pk2(a0.x, a0.x), vii0 = pk2(a0.y, a0.y);
            ull vrr1 = pk2(a1.x, a1.x), vii1 = pk2(a1.y, a1.y);
#pragma unroll
            for (int s = 0; s < 8; ++s) {
                ulonglong2 wp = *(ulonglong2*)&Wp[(wg * 8 + s) * KC + kk];
                fma2(acc[s][0], wp.x, vrr0);
                fma2(acc[s][0], wp.y, vii0);
                fma2(acc[s][1], wp.x, vrr1);
                fma2(acc[s][1], wp.y, vii1);
            }
        }
        __syncthreads();
    }
#pragma unroll
    for (int s = 0; s < 8; ++s) {
        int hp = wg * 8 + s;
        int h0 = 2 * hp, h1 = 2 * hp + 1;
#pragma unroll
        for (int r = 0; r < 2; ++r) {
            int col = (r == 0) ? c0 : c1;
            int l = l0 + col;
            if (l < L) {
                float e0, e1; upk2(acc[s][r], e0, e1);
                long long f0 = (long long)h0 * L + l;
                long long f1 = (long long)h1 * L + l;
                if (h0 < H && f0 < out_cap) out[f0] = e0;
                if (h1 < H && f1 < out_cap) out[f1] = e1;
            }
        }
    }
}

// ======================== launch ========================
extern "C" void kernel_launch(void* const* d_in, const int* in_sizes, int n_in,
                              void* d_out, int out_size) {
    int a_idx = -1, w_idx = -1;
    for (int i = 0; i < n_in; ++i) {
        if (in_sizes[i] <= 1) continue;
        if (a_idx < 0) { a_idx = i; }
        else if (w_idx < 0) {
            w_idx = i;
            if (in_sizes[a_idx] > in_sizes[w_idx]) { int t = a_idx; a_idx = w_idx; w_idx = t; }
        }
    }
    if (a_idx < 0 || w_idx < 0) return;

    const float* A = (const float*)d_in[a_idx];
    const float* W = (const float*)d_in[w_idx];
    float* out = (float*)d_out;

    int P = in_sizes[a_idx] / 2;
    int H = in_sizes[w_idx] / in_sizes[a_idx];
    if (P <= 0 || H <= 0) return;
    int L = out_size / H;
    if (L <= 0) return;

    int Pr = ((P + 31) / 32) * 32;
    bool conforming = (H <= HMAX) && (Pr <= PRMAX) &&
                      (L % TDL == 0) && (L >= LSPLIT) &&
                      ((long long)H * L <= (long long)HMAX * LMAX) &&
                      ((out_size & 3) == 0) && (Pr / 32 >= KS_HEAVY);

    if (conforming) {
        w_split_kernel<<<512, 256>>>(W, P, H, Pr);

        cudaFuncSetAttribute(mv_mma6_kernel,
                             cudaFuncAttributeMaxDynamicSharedMemorySize, SMEM_MMA);
        int tiles = L / TDL;
        int nheavy = LSPLIT / TDL;                    // 16
        int njobs = nheavy * KS_HEAVY + (tiles - nheavy) * KS_LIGHT;  // 320
        mv_mma6_kernel<<<njobs, 256, SMEM_MMA>>>(A, out, P, H, L, Pr,
                                                 (long long)out_size, nheavy);

        long long n4 = (long long)out_size / 4;
        int L4 = L / 4;
        int cblocks = (int)min((long long)2048, (n4 + 255) / 256);
        combine4_kernel<<<cblocks, 256>>>(out, n4, L4);
    } else {
        size_t smem = FB_SMEM_FIXED + (size_t)P * 8;
        cudaFuncSetAttribute(mv_gemm_kernel,
                             cudaFuncAttributeMaxDynamicSharedMemorySize, (int)smem);
        int grid = (L + TL - 1) / TL;
        mv_gemm_kernel<<<grid, FB_NT, smem>>>(A, W, out, P, H, L, (long long)out_size);
    }
}